// round 15
// baseline (speedup 1.0000x reference)
#include <cuda_runtime.h>
#include <cuda_fp16.h>
#include <cstdint>

// Problem constants (fixed by setup_inputs)
#define BATCH 4
#define IMG 256
#define WS 8
#define NW 1024              // (256/8)^2
#define BWIN (BATCH * NW)    // 4096 windows
#define NTOK 64              // WS*WS
#define CH 256
#define HEADS 8
#define HD 32
#define MTOT (BWIN * NTOK)   // 262144 rows

// Scratch (f16 pipeline)
__device__ __half g_xh[(size_t)MTOT * CH];
__device__ __half g_yh[(size_t)MTOT * CH];
__device__ __half g_Wqh[CH * CH];
__device__ __half g_Wkh[CH * CH];
__device__ __half g_Wvh[CH * CH];
__device__ __half g_Wph[CH * CH];
__device__ __half g_Q[(size_t)MTOT * CH];
__device__ __half g_K[(size_t)MTOT * CH];
__device__ __half g_V[(size_t)MTOT * CH];
__device__ __half g_S[(size_t)MTOT * CH];

// ---------------------------------------------------------------------------
// helpers
// ---------------------------------------------------------------------------
__device__ __forceinline__ uint32_t smem_u32(const void* p) {
    uint32_t a;
    asm("{ .reg .u64 t; cvta.to.shared.u64 t, %1; cvt.u32.u64 %0, t; }" : "=r"(a) : "l"(p));
    return a;
}
__device__ __forceinline__ void mma_f16(float* d, const uint32_t* a, const uint32_t* b) {
    asm volatile(
        "mma.sync.aligned.m16n8k16.row.col.f32.f16.f16.f32 "
        "{%0,%1,%2,%3}, {%4,%5,%6,%7}, {%8,%9}, {%0,%1,%2,%3};"
        : "+f"(d[0]), "+f"(d[1]), "+f"(d[2]), "+f"(d[3])
        : "r"(a[0]), "r"(a[1]), "r"(a[2]), "r"(a[3]), "r"(b[0]), "r"(b[1]));
}
__device__ __forceinline__ void ldsm4(uint32_t* r, uint32_t addr) {
    asm volatile("ldmatrix.sync.aligned.m8n8.x4.shared.b16 {%0,%1,%2,%3}, [%4];"
        : "=r"(r[0]), "=r"(r[1]), "=r"(r[2]), "=r"(r[3]) : "r"(addr));
}
__device__ __forceinline__ void ldsm4t(uint32_t* r, uint32_t addr) {
    asm volatile("ldmatrix.sync.aligned.m8n8.x4.trans.shared.b16 {%0,%1,%2,%3}, [%4];"
        : "=r"(r[0]), "=r"(r[1]), "=r"(r[2]), "=r"(r[3]) : "r"(addr));
}
__device__ __forceinline__ uint32_t h2u(__half2 h) { return *reinterpret_cast<uint32_t*>(&h); }
__device__ __forceinline__ void cp16(void* dst, const void* src) {
    uint32_t d = smem_u32(dst);
    asm volatile("cp.async.cg.shared.global [%0], [%1], 16;" :: "r"(d), "l"(src));
}
__device__ __forceinline__ void cp8(void* dst, const void* src) {
    uint32_t d = smem_u32(dst);
    asm volatile("cp.async.ca.shared.global [%0], [%1], 8;" :: "r"(d), "l"(src));
}
#define CP_COMMIT() asm volatile("cp.async.commit_group;" ::: "memory")
#define CP_WAIT0()  asm volatile("cp.async.wait_group 0;" ::: "memory")

// ---------------------------------------------------------------------------
// fp32 -> f16 convert (streaming, 8 elem/thread)
// ---------------------------------------------------------------------------
__global__ __launch_bounds__(256) void cvt_f16(
    const float* __restrict__ in, __half* __restrict__ out)
{
    size_t i = ((size_t)blockIdx.x * 256 + threadIdx.x) * 8;
    float4 a = *(const float4*)(in + i);
    float4 b = *(const float4*)(in + i + 4);
    uint4 o;
    o.x = h2u(__floats2half2_rn(a.x, a.y));
    o.y = h2u(__floats2half2_rn(a.z, a.w));
    o.z = h2u(__floats2half2_rn(b.x, b.y));
    o.w = h2u(__floats2half2_rn(b.z, b.w));
    *(uint4*)(out + i) = o;
}

// ---------------------------------------------------------------------------
// GEMM f16: tile 64(M) x 128(N), KC=64, 2-stage buffer = 55.3 KB smem,
// 128 threads (4 warps), warp tile 64x32 (same issue ratio as 128x128 cfg),
// __launch_bounds__(128,4) -> up to 4 CTAs/SM.
// wsel = blockIdx.x >> 1 picks (A, W, bias, C) triple; n0 = (blockIdx.x&1)*128.
// ---------------------------------------------------------------------------
#define KC 64
#define GSTR 72
#define GEMM_SMEM (2 * (64 + 128) * GSTR * 2)   // 55296 B

template <typename OutT>
__global__ __launch_bounds__(128, 4) void gemm_f16k(
    const __half* __restrict__ A0, const __half* __restrict__ A1,
    const __half* __restrict__ W0, const __half* __restrict__ W1,
    const __half* __restrict__ W2,
    const float* __restrict__ b0, const float* __restrict__ b1,
    const float* __restrict__ b2,
    OutT* __restrict__ C0, OutT* __restrict__ C1, OutT* __restrict__ C2)
{
    extern __shared__ __half hsm[];
    __half* Ah = hsm;                    // [2][64*GSTR]
    __half* Bh = hsm + 2 * 64 * GSTR;    // [2][128*GSTR]

    const int wsel = blockIdx.x >> 1;
    const int n0 = (blockIdx.x & 1) * 128;
    const __half* A  = (wsel == 2) ? A1 : A0;
    const __half* Wt = (wsel == 0) ? W0 : (wsel == 1) ? W1 : W2;
    const float* bias = (wsel == 0) ? b0 : (wsel == 1) ? b1 : b2;
    OutT* C = (wsel == 0) ? C0 : (wsel == 1) ? C1 : C2;

    const int t = threadIdx.x, lane = t & 31, warp = t >> 5;
    const int wn = warp;                 // 4 n-subtiles of 32
    const int m0 = blockIdx.y * 64;
    const int g = lane >> 2, tg = lane & 3;

    const uint32_t aBase = smem_u32(Ah), bBase = smem_u32(Bh);
    const int lmrow = lane & 15, lmk = (lane >> 4) << 3;
    const int bg2 = lane >> 3, bj = lane & 7;

    float acc[4][4][4];
#pragma unroll
    for (int mi = 0; mi < 4; mi++)
#pragma unroll
        for (int ni = 0; ni < 4; ni++)
#pragma unroll
            for (int r = 0; r < 4; r++) acc[mi][ni][r] = 0.f;

    // loaders: A 64 rows x 8 cp16 (2 thr/row, 4 each); B 128 rows x 8 cp16 (1 thr/row)
    const int ar = t >> 1, ac = (t & 1) * 32;

    {
#pragma unroll
        for (int i = 0; i < 4; i++)
            cp16(Ah + ar * GSTR + ac + i * 8, A + (size_t)(m0 + ar) * 256 + ac + i * 8);
#pragma unroll
        for (int i = 0; i < 8; i++)
            cp16(Bh + t * GSTR + i * 8, Wt + (size_t)(n0 + t) * 256 + i * 8);
        CP_COMMIT();
    }

    for (int kc = 0; kc < 4; kc++) {
        CP_WAIT0();
        __syncthreads();
        if (kc < 3) {
            const int ko = (kc + 1) * KC;
            __half* Ad = Ah + ((kc + 1) & 1) * 64 * GSTR;
            __half* Bd = Bh + ((kc + 1) & 1) * 128 * GSTR;
#pragma unroll
            for (int i = 0; i < 4; i++)
                cp16(Ad + ar * GSTR + ac + i * 8, A + (size_t)(m0 + ar) * 256 + ko + ac + i * 8);
#pragma unroll
            for (int i = 0; i < 8; i++)
                cp16(Bd + t * GSTR + i * 8, Wt + (size_t)(n0 + t) * 256 + ko + i * 8);
            CP_COMMIT();
        }
        const uint32_t aB = aBase + (uint32_t)((kc & 1) * 64 * GSTR) * 2;
        const uint32_t bB = bBase + (uint32_t)((kc & 1) * 128 * GSTR) * 2;
#pragma unroll
        for (int ks = 0; ks < 4; ks++) {
            const int k0h = ks * 16;
            uint32_t a[4][4], b[4][2];
#pragma unroll
            for (int mi = 0; mi < 4; mi++)
                ldsm4(a[mi], aB + (uint32_t)((mi * 16 + lmrow) * GSTR + k0h + lmk) * 2);
#pragma unroll
            for (int p = 0; p < 2; p++) {
                uint32_t r4[4];
                ldsm4(r4, bB + (uint32_t)((wn * 32 + p * 16 + ((bg2 >> 1) << 3) + bj) * GSTR
                                          + k0h + ((bg2 & 1) << 3)) * 2);
                b[2 * p][0] = r4[0]; b[2 * p][1] = r4[1];
                b[2 * p + 1][0] = r4[2]; b[2 * p + 1][1] = r4[3];
            }
#pragma unroll
            for (int mi = 0; mi < 4; mi++)
#pragma unroll
                for (int ni = 0; ni < 4; ni++)
                    mma_f16(acc[mi][ni], a[mi], b[ni]);
        }
        __syncthreads();
    }

    float bv[4][2];
#pragma unroll
    for (int ni = 0; ni < 4; ni++) {
        int col = n0 + wn * 32 + ni * 8 + 2 * tg;
        bv[ni][0] = __ldg(bias + col);
        bv[ni][1] = __ldg(bias + col + 1);
    }
#pragma unroll
    for (int mi = 0; mi < 4; mi++) {
        int r0 = m0 + mi * 16 + g;
#pragma unroll
        for (int ni = 0; ni < 4; ni++) {
            int col = n0 + wn * 32 + ni * 8 + 2 * tg;
            if constexpr (sizeof(OutT) == 2) {
                *(__half2*)((__half*)C + (size_t)r0 * 256 + col) =
                    __floats2half2_rn(acc[mi][ni][0] + bv[ni][0], acc[mi][ni][1] + bv[ni][1]);
                *(__half2*)((__half*)C + (size_t)(r0 + 8) * 256 + col) =
                    __floats2half2_rn(acc[mi][ni][2] + bv[ni][0], acc[mi][ni][3] + bv[ni][1]);
            } else {
                *(float2*)((float*)C + (size_t)r0 * 256 + col) =
                    make_float2(acc[mi][ni][0] + bv[ni][0], acc[mi][ni][1] + bv[ni][1]);
                *(float2*)((float*)C + (size_t)(r0 + 8) * 256 + col) =
                    make_float2(acc[mi][ni][2] + bv[ni][0], acc[mi][ni][3] + bv[ni][1]);
            }
        }
    }
}

// ---------------------------------------------------------------------------
// Attention f16 + fused LePE (round-11/12 structure, unchanged)
// ---------------------------------------------------------------------------
#define AST 72
#define HSTR 68
#define ATTN_SMEM 53024

__global__ __launch_bounds__(128, 4) void attn_lepe(
    const __half* __restrict__ Q, const __half* __restrict__ K,
    const __half* __restrict__ V, const float* __restrict__ mask,
    const float* __restrict__ rw, const float* __restrict__ rb,
    __half* __restrict__ S)
{
    extern __shared__ __half asmh[];
    __half* Kh   = asmh;
    __half* Vs   = asmh + 4608;
    __half* Pp   = asmh + 9216;
    __half* Halo = asmh + 18432;
    float*  Wsm  = (float*)(asmh + 25232);
    float*  Bsm  = Wsm + 576;

    const int hp = blockIdx.x;
    const int b  = blockIdx.y;
    const int t = threadIdx.x, lane = t & 31, w = t >> 5;
    const int g = lane >> 2, tg = lane & 3;
    const int bg2 = lane >> 3, bj = lane & 7;
    const int lmrow = lane & 15, lmk = (lane >> 4) << 3;
    const size_t base = (size_t)b * NTOK * CH + hp * 64;
    const float scale = 0.17677669529663687f;

    const int bi = b >> 10, win = b & 1023;
    const int hh0 = (win >> 5) * 8, ww0 = (win & 31) * 8;
#pragma unroll
    for (int i = t; i < 160; i += 128) {
        if (i < 144) cp16(Wsm + i * 4, rw + (size_t)hp * 576 + i * 4);
        else         cp16(Bsm + (i - 144) * 4, rb + hp * 64 + (i - 144) * 4);
    }
#pragma unroll
    for (int i = 0; i < 13; i++) {
        int linear = t + i * 128;
        if (linear < 1600) {
            int p = linear >> 4, c4 = (linear & 15) * 4;
            int py = p / 10, px = p % 10;
            int hh = hh0 + py - 1, ww = ww0 + px - 1;
            __half* dst = Halo + p * HSTR + c4;
            if (hh >= 0 && hh < IMG && ww >= 0 && ww < IMG) {
                size_t src = ((size_t)(bi * NW + (hh >> 3) * 32 + (ww >> 3)) * NTOK
                              + ((hh & 7) * 8 + (ww & 7))) * CH + hp * 64 + c4;
                cp8(dst, Q + src);
            } else {
                *(uint2*)dst = make_uint2(0u, 0u);
            }
        }
    }
    CP_COMMIT();

#pragma unroll
    for (int i = 0; i < 8; i++) {
        int linear = i * 128 + t;
        int row = linear >> 4;
        int c4 = (linear & 15) * 4;
        *(uint2*)(Kh + row * AST + c4) = *(const uint2*)(K + base + (size_t)row * 256 + c4);
        *(uint2*)(Vs + row * AST + c4) = *(const uint2*)(V + base + (size_t)row * 256 + c4);
    }
    __syncthreads();

    const int ch0 = (w >> 1) * 32;
    const int rbase = (w & 1) * 32;

    const __half* Qr[2][2];
#pragma unroll
    for (int mi = 0; mi < 2; mi++) {
        int r = rbase + mi * 16 + g;
        Qr[mi][0] = Q + base + (size_t)r * 256 + ch0;
        Qr[mi][1] = Q + base + (size_t)(r + 8) * 256 + ch0;
    }

    const uint32_t KhA = smem_u32(Kh), VsA = smem_u32(Vs);

    float acc[2][8][4];
#pragma unroll
    for (int mi = 0; mi < 2; mi++)
#pragma unroll
        for (int ni = 0; ni < 8; ni++)
#pragma unroll
            for (int r = 0; r < 4; r++) acc[mi][ni][r] = 0.f;

#pragma unroll
    for (int ks = 0; ks < 2; ks++) {
        uint32_t a[2][4], bb[8][2];
#pragma unroll
        for (int mi = 0; mi < 2; mi++) {
            a[mi][0] = *(const uint32_t*)(Qr[mi][0] + ks * 16 + 2 * tg);
            a[mi][1] = *(const uint32_t*)(Qr[mi][1] + ks * 16 + 2 * tg);
            a[mi][2] = *(const uint32_t*)(Qr[mi][0] + ks * 16 + 8 + 2 * tg);
            a[mi][3] = *(const uint32_t*)(Qr[mi][1] + ks * 16 + 8 + 2 * tg);
        }
#pragma unroll
        for (int p = 0; p < 4; p++) {
            uint32_t r4[4];
            ldsm4(r4, KhA + (uint32_t)((p * 16 + ((bg2 >> 1) << 3) + bj) * AST
                                       + ch0 + ks * 16 + ((bg2 & 1) << 3)) * 2);
            bb[2 * p][0] = r4[0]; bb[2 * p][1] = r4[1];
            bb[2 * p + 1][0] = r4[2]; bb[2 * p + 1][1] = r4[3];
        }
#pragma unroll
        for (int mi = 0; mi < 2; mi++)
#pragma unroll
            for (int ni = 0; ni < 8; ni++)
                mma_f16(acc[mi][ni], a[mi], bb[ni]);
    }

    const float* mp = mask + (size_t)(b & (NW - 1)) * NTOK * NTOK;
#pragma unroll
    for (int mi = 0; mi < 2; mi++) {
#pragma unroll
        for (int rh = 0; rh < 2; rh++) {
            const int row = rbase + mi * 16 + rh * 8 + g;
            const int o = rh * 2;
            float mx = -1e30f;
#pragma unroll
            for (int ni = 0; ni < 8; ni++) {
                float2 mv = *(const float2*)(mp + row * 64 + ni * 8 + 2 * tg);
                acc[mi][ni][o]     = fmaf(acc[mi][ni][o], scale, mv.x);
                acc[mi][ni][o + 1] = fmaf(acc[mi][ni][o + 1], scale, mv.y);
                mx = fmaxf(mx, fmaxf(acc[mi][ni][o], acc[mi][ni][o + 1]));
            }
            mx = fmaxf(mx, __shfl_xor_sync(0xffffffffu, mx, 1));
            mx = fmaxf(mx, __shfl_xor_sync(0xffffffffu, mx, 2));
            float sum = 0.f;
#pragma unroll
            for (int ni = 0; ni < 8; ni++) {
                acc[mi][ni][o]     = __expf(acc[mi][ni][o] - mx);
                acc[mi][ni][o + 1] = __expf(acc[mi][ni][o + 1] - mx);
                sum += acc[mi][ni][o] + acc[mi][ni][o + 1];
            }
            sum += __shfl_xor_sync(0xffffffffu, sum, 1);
            sum += __shfl_xor_sync(0xffffffffu, sum, 2);
            const float inv = 1.f / sum;
#pragma unroll
            for (int ni = 0; ni < 8; ni++) {
                acc[mi][ni][o]     *= inv;
                acc[mi][ni][o + 1] *= inv;
            }
        }
    }

    __half* Pw = Pp + w * 32 * AST;
#pragma unroll
    for (int mi = 0; mi < 2; mi++)
#pragma unroll
        for (int rh = 0; rh < 2; rh++) {
            const int rl = mi * 16 + rh * 8 + g;
#pragma unroll
            for (int ni = 0; ni < 8; ni++)
                *(__half2*)(Pw + rl * AST + ni * 8 + 2 * tg) =
                    __floats2half2_rn(acc[mi][ni][rh * 2], acc[mi][ni][rh * 2 + 1]);
        }
    __syncwarp();

    const uint32_t PwA = smem_u32(Pw);
    float acc2[2][4][4];
#pragma unroll
    for (int mi = 0; mi < 2; mi++)
#pragma unroll
        for (int ni = 0; ni < 4; ni++)
#pragma unroll
            for (int r = 0; r < 4; r++) acc2[mi][ni][r] = 0.f;

#pragma unroll
    for (int ks = 0; ks < 4; ks++) {
        uint32_t a[2][4], bb[4][2];
#pragma unroll
        for (int mi = 0; mi < 2; mi++)
            ldsm4(a[mi], PwA + (uint32_t)((mi * 16 + lmrow) * AST + ks * 16 + lmk) * 2);
#pragma unroll
        for (int p = 0; p < 2; p++) {
            uint32_t r4[4];
            int tok = ks * 16 + ((bg2 & 1) << 3) + bj;
            int chc = ch0 + p * 16 + ((bg2 >> 1) << 3);
            ldsm4t(r4, VsA + (uint32_t)(tok * AST + chc) * 2);
            bb[2 * p][0] = r4[0]; bb[2 * p][1] = r4[1];
            bb[2 * p + 1][0] = r4[2]; bb[2 * p + 1][1] = r4[3];
        }
#pragma unroll
        for (int mi = 0; mi < 2; mi++)
#pragma unroll
            for (int ni = 0; ni < 4; ni++)
                mma_f16(acc2[mi][ni], a[mi], bb[ni]);
    }

    CP_WAIT0();
    __syncthreads();

#pragma unroll
    for (int mi = 0; mi < 2; mi++) {
#pragma unroll
        for (int rh = 0; rh < 2; rh++) {
            const int row = rbase + mi * 16 + rh * 8 + g;
            const int py = row >> 3, px = row & 7;
#pragma unroll
            for (int ni = 0; ni < 4; ni++) {
#pragma unroll
                for (int c2 = 0; c2 < 2; c2++) {
                    const int c = ch0 + ni * 8 + 2 * tg + c2;
                    const float* wc9 = Wsm + c * 9;
                    float v = Bsm[c];
#pragma unroll
                    for (int dy = 0; dy < 3; dy++)
#pragma unroll
                        for (int dx = 0; dx < 3; dx++)
                            v = fmaf(__half2float(Halo[((py + dy) * 10 + px + dx) * HSTR + c]),
                                     wc9[dy * 3 + dx], v);
                    acc2[mi][ni][rh * 2 + c2] += v;
                }
            }
        }
    }

#pragma unroll
    for (int mi = 0; mi < 2; mi++) {
        const int row = rbase + mi * 16 + g;
#pragma unroll
        for (int ni = 0; ni < 4; ni++) {
            const int col = hp * 64 + ch0 + ni * 8 + 2 * tg;
            *(__half2*)(S + (size_t)(b * NTOK + row) * 256 + col) =
                __floats2half2_rn(acc2[mi][ni][0], acc2[mi][ni][1]);
            *(__half2*)(S + (size_t)(b * NTOK + row + 8) * 256 + col) =
                __floats2half2_rn(acc2[mi][ni][2], acc2[mi][ni][3]);
        }
    }
}

// ---------------------------------------------------------------------------
// kernel_launch
// ---------------------------------------------------------------------------
extern "C" void kernel_launch(void* const* d_in, const int* in_sizes, int n_in,
                              void* d_out, int out_size)
{
    const float* x    = (const float*)d_in[0];
    const float* y    = (const float*)d_in[1];
    const float* mask = (const float*)d_in[2];
    const float* Wq   = (const float*)d_in[3];
    const float* bq   = (const float*)d_in[4];
    const float* Wk   = (const float*)d_in[5];
    const float* bk   = (const float*)d_in[6];
    const float* Wv   = (const float*)d_in[7];
    const float* bv   = (const float*)d_in[8];
    const float* rw   = (const float*)d_in[9];
    const float* rb   = (const float*)d_in[10];
    const float* Wp   = (const float*)d_in[11];
    const float* bp   = (const float*)d_in[12];
    float* out        = (float*)d_out;

    __half *pxh, *pyh, *pWq, *pWk, *pWv, *pWp, *pQ, *pK, *pV, *pS;
    cudaGetSymbolAddress((void**)&pxh, g_xh);
    cudaGetSymbolAddress((void**)&pyh, g_yh);
    cudaGetSymbolAddress((void**)&pWq, g_Wqh);
    cudaGetSymbolAddress((void**)&pWk, g_Wkh);
    cudaGetSymbolAddress((void**)&pWv, g_Wvh);
    cudaGetSymbolAddress((void**)&pWp, g_Wph);
    cudaGetSymbolAddress((void**)&pQ, g_Q);
    cudaGetSymbolAddress((void**)&pK, g_K);
    cudaGetSymbolAddress((void**)&pV, g_V);
    cudaGetSymbolAddress((void**)&pS, g_S);

    static bool attr_done = false;
    if (!attr_done) {
        cudaFuncSetAttribute(gemm_f16k<__half>, cudaFuncAttributeMaxDynamicSharedMemorySize, GEMM_SMEM);
        cudaFuncSetAttribute(gemm_f16k<float>,  cudaFuncAttributeMaxDynamicSharedMemorySize, GEMM_SMEM);
        cudaFuncSetAttribute(attn_lepe, cudaFuncAttributeMaxDynamicSharedMemorySize, ATTN_SMEM);
        attr_done = true;
    }

    const int NBIG = (int)((size_t)MTOT * CH / (256 * 8));   // 32768 blocks
    const int NW2 = CH * CH / (256 * 8);                      // 32 blocks
    cvt_f16<<<NBIG, 256>>>(x, pxh);
    cvt_f16<<<NBIG, 256>>>(y, pyh);
    cvt_f16<<<NW2, 256>>>(Wq, pWq);
    cvt_f16<<<NW2, 256>>>(Wk, pWk);
    cvt_f16<<<NW2, 256>>>(Wv, pWv);
    cvt_f16<<<NW2, 256>>>(Wp, pWp);

    // Q, V, K in ONE launch: wsel = blockIdx.x>>1 -> {x*Wq, x*Wv, y*Wk}
    gemm_f16k<__half><<<dim3(6, MTOT / 64), 128, GEMM_SMEM>>>(
        pxh, pyh, pWq, pWv, pWk, bq, bv, bk, pQ, pV, pK);

    attn_lepe<<<dim3(4, BWIN), 128, ATTN_SMEM>>>(pQ, pK, pV, mask, rw, rb, pS);

    gemm_f16k<float><<<dim3(2, MTOT / 64), 128, GEMM_SMEM>>>(
        pS, pS, pWp, pWp, pWp, bp, bp, bp, out, out, out);
}

// round 16
// speedup vs baseline: 1.4174x; 1.4174x over previous
#include <cuda_runtime.h>
#include <cuda_fp16.h>
#include <cstdint>

// Problem constants (fixed by setup_inputs)
#define BATCH 4
#define IMG 256
#define WS 8
#define NW 1024              // (256/8)^2
#define BWIN (BATCH * NW)    // 4096 windows
#define NTOK 64              // WS*WS
#define CH 256
#define HEADS 8
#define HD 32
#define MTOT (BWIN * NTOK)   // 262144 rows

// Scratch (f16 pipeline)
__device__ __half g_xh[(size_t)MTOT * CH];
__device__ __half g_yh[(size_t)MTOT * CH];
__device__ __half g_Wqh[CH * CH];
__device__ __half g_Wkh[CH * CH];
__device__ __half g_Wvh[CH * CH];
__device__ __half g_Wph[CH * CH];
__device__ __half g_Q[(size_t)MTOT * CH];
__device__ __half g_K[(size_t)MTOT * CH];
__device__ __half g_V[(size_t)MTOT * CH];
__device__ __half g_S[(size_t)MTOT * CH];

// ---------------------------------------------------------------------------
// helpers
// ---------------------------------------------------------------------------
__device__ __forceinline__ uint32_t smem_u32(const void* p) {
    uint32_t a;
    asm("{ .reg .u64 t; cvta.to.shared.u64 t, %1; cvt.u32.u64 %0, t; }" : "=r"(a) : "l"(p));
    return a;
}
__device__ __forceinline__ void mma_f16(float* d, const uint32_t* a, const uint32_t* b) {
    asm volatile(
        "mma.sync.aligned.m16n8k16.row.col.f32.f16.f16.f32 "
        "{%0,%1,%2,%3}, {%4,%5,%6,%7}, {%8,%9}, {%0,%1,%2,%3};"
        : "+f"(d[0]), "+f"(d[1]), "+f"(d[2]), "+f"(d[3])
        : "r"(a[0]), "r"(a[1]), "r"(a[2]), "r"(a[3]), "r"(b[0]), "r"(b[1]));
}
__device__ __forceinline__ void ldsm4(uint32_t* r, uint32_t addr) {
    asm volatile("ldmatrix.sync.aligned.m8n8.x4.shared.b16 {%0,%1,%2,%3}, [%4];"
        : "=r"(r[0]), "=r"(r[1]), "=r"(r[2]), "=r"(r[3]) : "r"(addr));
}
__device__ __forceinline__ void ldsm4t(uint32_t* r, uint32_t addr) {
    asm volatile("ldmatrix.sync.aligned.m8n8.x4.trans.shared.b16 {%0,%1,%2,%3}, [%4];"
        : "=r"(r[0]), "=r"(r[1]), "=r"(r[2]), "=r"(r[3]) : "r"(addr));
}
__device__ __forceinline__ uint32_t h2u(__half2 h) { return *reinterpret_cast<uint32_t*>(&h); }
__device__ __forceinline__ void cp16(void* dst, const void* src) {
    uint32_t d = smem_u32(dst);
    asm volatile("cp.async.cg.shared.global [%0], [%1], 16;" :: "r"(d), "l"(src));
}
__device__ __forceinline__ void cp8(void* dst, const void* src) {
    uint32_t d = smem_u32(dst);
    asm volatile("cp.async.ca.shared.global [%0], [%1], 8;" :: "r"(d), "l"(src));
}
#define CP_COMMIT() asm volatile("cp.async.commit_group;" ::: "memory")
#define CP_WAIT0()  asm volatile("cp.async.wait_group 0;" ::: "memory")

// ---------------------------------------------------------------------------
// fp32 -> f16 convert (streaming, 8 elem/thread)
// ---------------------------------------------------------------------------
__global__ __launch_bounds__(256) void cvt_f16(
    const float* __restrict__ in, __half* __restrict__ out)
{
    size_t i = ((size_t)blockIdx.x * 256 + threadIdx.x) * 8;
    float4 a = *(const float4*)(in + i);
    float4 b = *(const float4*)(in + i + 4);
    uint4 o;
    o.x = h2u(__floats2half2_rn(a.x, a.y));
    o.y = h2u(__floats2half2_rn(a.z, a.w));
    o.z = h2u(__floats2half2_rn(b.x, b.y));
    o.w = h2u(__floats2half2_rn(b.z, b.w));
    *(uint4*)(out + i) = o;
}

// convert 4 weight matrices in one launch; 32 blocks per matrix
__global__ __launch_bounds__(256) void cvt_w4(
    const float* __restrict__ w0, const float* __restrict__ w1,
    const float* __restrict__ w2, const float* __restrict__ w3,
    __half* __restrict__ o0, __half* __restrict__ o1,
    __half* __restrict__ o2, __half* __restrict__ o3)
{
    const int sel = blockIdx.x >> 5;
    const int blk = blockIdx.x & 31;
    const float* in = (sel == 0) ? w0 : (sel == 1) ? w1 : (sel == 2) ? w2 : w3;
    __half* out = (sel == 0) ? o0 : (sel == 1) ? o1 : (sel == 2) ? o2 : o3;
    size_t i = ((size_t)blk * 256 + threadIdx.x) * 8;
    float4 a = *(const float4*)(in + i);
    float4 b = *(const float4*)(in + i + 4);
    uint4 o;
    o.x = h2u(__floats2half2_rn(a.x, a.y));
    o.y = h2u(__floats2half2_rn(a.z, a.w));
    o.z = h2u(__floats2half2_rn(b.x, b.y));
    o.w = h2u(__floats2half2_rn(b.z, b.w));
    *(uint4*)(out + i) = o;
}

// ---------------------------------------------------------------------------
// GEMM pure f16 (round-11 structure: 128x128 tile, 256 thr, warp 64x32).
// wsel = blockIdx.x >> 1 selects (A, W, bias, C); n0 = (blockIdx.x & 1)*128.
// ---------------------------------------------------------------------------
#define KC 64
#define GSTR 72
#define GEMM_SMEM (2 * 2 * 128 * GSTR * 2)   // 73728 B

__device__ __forceinline__ void load_chunk_async(
    const __half* Ap, const __half* Bp, __half* Ad, __half* Bd, int t)
{
    const int c16 = (t & 7) * 8;
    const int row0 = t >> 3;
#pragma unroll
    for (int i = 0; i < 4; i++) {
        int row = row0 + i * 32;
        cp16(Ad + row * GSTR + c16, Ap + (size_t)row * 256 + c16);
        cp16(Bd + row * GSTR + c16, Bp + (size_t)row * 256 + c16);
    }
}

template <typename OutT>
__global__ __launch_bounds__(256) void gemm_f16k(
    const __half* __restrict__ A0, const __half* __restrict__ A1,
    const __half* __restrict__ W0, const __half* __restrict__ W1,
    const __half* __restrict__ W2,
    const float* __restrict__ b0, const float* __restrict__ b1,
    const float* __restrict__ b2,
    OutT* __restrict__ C0, OutT* __restrict__ C1, OutT* __restrict__ C2)
{
    extern __shared__ __half hsm[];
    __half* Ah = hsm;
    __half* Bh = hsm + 2 * 128 * GSTR;

    const int wsel = blockIdx.x >> 1;
    const int n0 = (blockIdx.x & 1) * 128;
    const __half* A  = (wsel == 2) ? A1 : A0;
    const __half* Wt = (wsel == 0) ? W0 : (wsel == 1) ? W1 : W2;
    const float* bias = (wsel == 0) ? b0 : (wsel == 1) ? b1 : b2;
    OutT* C = (wsel == 0) ? C0 : (wsel == 1) ? C1 : C2;

    const int t = threadIdx.x, lane = t & 31, warp = t >> 5;
    const int wm = warp & 1, wn = warp >> 1;
    const int m0 = blockIdx.y * 128;
    const int g = lane >> 2, tg = lane & 3;

    const uint32_t aBase = smem_u32(Ah), bBase = smem_u32(Bh);
    const int lmrow = lane & 15, lmk = (lane >> 4) << 3;
    const int bg2 = lane >> 3, bj = lane & 7;

    float acc[4][4][4];
#pragma unroll
    for (int mi = 0; mi < 4; mi++)
#pragma unroll
        for (int ni = 0; ni < 4; ni++)
#pragma unroll
            for (int r = 0; r < 4; r++) acc[mi][ni][r] = 0.f;

    load_chunk_async(A + (size_t)m0 * 256, Wt + (size_t)n0 * 256, Ah, Bh, t);
    CP_COMMIT();

    for (int kc = 0; kc < 4; kc++) {
        CP_WAIT0();
        __syncthreads();
        if (kc < 3) {
            int buf = (kc + 1) & 1;
            load_chunk_async(A + (size_t)m0 * 256 + (kc + 1) * KC,
                             Wt + (size_t)n0 * 256 + (kc + 1) * KC,
                             Ah + buf * 128 * GSTR, Bh + buf * 128 * GSTR, t);
            CP_COMMIT();
        }
        const uint32_t aB = aBase + (uint32_t)((kc & 1) * 128 * GSTR) * 2;
        const uint32_t bB = bBase + (uint32_t)((kc & 1) * 128 * GSTR) * 2;
#pragma unroll
        for (int ks = 0; ks < 4; ks++) {
            const int k0h = ks * 16;
            uint32_t a[4][4], b[4][2];
#pragma unroll
            for (int mi = 0; mi < 4; mi++)
                ldsm4(a[mi], aB + (uint32_t)((wm * 64 + mi * 16 + lmrow) * GSTR + k0h + lmk) * 2);
#pragma unroll
            for (int p = 0; p < 2; p++) {
                uint32_t r4[4];
                ldsm4(r4, bB + (uint32_t)((wn * 32 + p * 16 + ((bg2 >> 1) << 3) + bj) * GSTR
                                          + k0h + ((bg2 & 1) << 3)) * 2);
                b[2 * p][0] = r4[0]; b[2 * p][1] = r4[1];
                b[2 * p + 1][0] = r4[2]; b[2 * p + 1][1] = r4[3];
            }
#pragma unroll
            for (int mi = 0; mi < 4; mi++)
#pragma unroll
                for (int ni = 0; ni < 4; ni++)
                    mma_f16(acc[mi][ni], a[mi], b[ni]);
        }
        __syncthreads();
    }

    float bv[4][2];
#pragma unroll
    for (int ni = 0; ni < 4; ni++) {
        int col = n0 + wn * 32 + ni * 8 + 2 * tg;
        bv[ni][0] = __ldg(bias + col);
        bv[ni][1] = __ldg(bias + col + 1);
    }
#pragma unroll
    for (int mi = 0; mi < 4; mi++) {
        int r0 = m0 + wm * 64 + mi * 16 + g;
#pragma unroll
        for (int ni = 0; ni < 4; ni++) {
            int col = n0 + wn * 32 + ni * 8 + 2 * tg;
            if constexpr (sizeof(OutT) == 2) {
                *(__half2*)((__half*)C + (size_t)r0 * 256 + col) =
                    __floats2half2_rn(acc[mi][ni][0] + bv[ni][0], acc[mi][ni][1] + bv[ni][1]);
                *(__half2*)((__half*)C + (size_t)(r0 + 8) * 256 + col) =
                    __floats2half2_rn(acc[mi][ni][2] + bv[ni][0], acc[mi][ni][3] + bv[ni][1]);
            } else {
                *(float2*)((float*)C + (size_t)r0 * 256 + col) =
                    make_float2(acc[mi][ni][0] + bv[ni][0], acc[mi][ni][1] + bv[ni][1]);
                *(float2*)((float*)C + (size_t)(r0 + 8) * 256 + col) =
                    make_float2(acc[mi][ni][2] + bv[ni][0], acc[mi][ni][3] + bv[ni][1]);
            }
        }
    }
}

// ---------------------------------------------------------------------------
// Attention f16 + fused LePE (round-11 structure, unchanged)
// ---------------------------------------------------------------------------
#define AST 72
#define HSTR 68
#define ATTN_SMEM 53024

__global__ __launch_bounds__(128, 4) void attn_lepe(
    const __half* __restrict__ Q, const __half* __restrict__ K,
    const __half* __restrict__ V, const float* __restrict__ mask,
    const float* __restrict__ rw, const float* __restrict__ rb,
    __half* __restrict__ S)
{
    extern __shared__ __half asmh[];
    __half* Kh   = asmh;
    __half* Vs   = asmh + 4608;
    __half* Pp   = asmh + 9216;
    __half* Halo = asmh + 18432;
    float*  Wsm  = (float*)(asmh + 25232);
    float*  Bsm  = Wsm + 576;

    const int hp = blockIdx.x;
    const int b  = blockIdx.y;
    const int t = threadIdx.x, lane = t & 31, w = t >> 5;
    const int g = lane >> 2, tg = lane & 3;
    const int bg2 = lane >> 3, bj = lane & 7;
    const int lmrow = lane & 15, lmk = (lane >> 4) << 3;
    const size_t base = (size_t)b * NTOK * CH + hp * 64;
    const float scale = 0.17677669529663687f;

    const int bi = b >> 10, win = b & 1023;
    const int hh0 = (win >> 5) * 8, ww0 = (win & 31) * 8;
#pragma unroll
    for (int i = t; i < 160; i += 128) {
        if (i < 144) cp16(Wsm + i * 4, rw + (size_t)hp * 576 + i * 4);
        else         cp16(Bsm + (i - 144) * 4, rb + hp * 64 + (i - 144) * 4);
    }
#pragma unroll
    for (int i = 0; i < 13; i++) {
        int linear = t + i * 128;
        if (linear < 1600) {
            int p = linear >> 4, c4 = (linear & 15) * 4;
            int py = p / 10, px = p % 10;
            int hh = hh0 + py - 1, ww = ww0 + px - 1;
            __half* dst = Halo + p * HSTR + c4;
            if (hh >= 0 && hh < IMG && ww >= 0 && ww < IMG) {
                size_t src = ((size_t)(bi * NW + (hh >> 3) * 32 + (ww >> 3)) * NTOK
                              + ((hh & 7) * 8 + (ww & 7))) * CH + hp * 64 + c4;
                cp8(dst, Q + src);
            } else {
                *(uint2*)dst = make_uint2(0u, 0u);
            }
        }
    }
    CP_COMMIT();

#pragma unroll
    for (int i = 0; i < 8; i++) {
        int linear = i * 128 + t;
        int row = linear >> 4;
        int c4 = (linear & 15) * 4;
        *(uint2*)(Kh + row * AST + c4) = *(const uint2*)(K + base + (size_t)row * 256 + c4);
        *(uint2*)(Vs + row * AST + c4) = *(const uint2*)(V + base + (size_t)row * 256 + c4);
    }
    __syncthreads();

    const int ch0 = (w >> 1) * 32;
    const int rbase = (w & 1) * 32;

    const __half* Qr[2][2];
#pragma unroll
    for (int mi = 0; mi < 2; mi++) {
        int r = rbase + mi * 16 + g;
        Qr[mi][0] = Q + base + (size_t)r * 256 + ch0;
        Qr[mi][1] = Q + base + (size_t)(r + 8) * 256 + ch0;
    }

    const uint32_t KhA = smem_u32(Kh), VsA = smem_u32(Vs);

    float acc[2][8][4];
#pragma unroll
    for (int mi = 0; mi < 2; mi++)
#pragma unroll
        for (int ni = 0; ni < 8; ni++)
#pragma unroll
            for (int r = 0; r < 4; r++) acc[mi][ni][r] = 0.f;

#pragma unroll
    for (int ks = 0; ks < 2; ks++) {
        uint32_t a[2][4], bb[8][2];
#pragma unroll
        for (int mi = 0; mi < 2; mi++) {
            a[mi][0] = *(const uint32_t*)(Qr[mi][0] + ks * 16 + 2 * tg);
            a[mi][1] = *(const uint32_t*)(Qr[mi][1] + ks * 16 + 2 * tg);
            a[mi][2] = *(const uint32_t*)(Qr[mi][0] + ks * 16 + 8 + 2 * tg);
            a[mi][3] = *(const uint32_t*)(Qr[mi][1] + ks * 16 + 8 + 2 * tg);
        }
#pragma unroll
        for (int p = 0; p < 4; p++) {
            uint32_t r4[4];
            ldsm4(r4, KhA + (uint32_t)((p * 16 + ((bg2 >> 1) << 3) + bj) * AST
                                       + ch0 + ks * 16 + ((bg2 & 1) << 3)) * 2);
            bb[2 * p][0] = r4[0]; bb[2 * p][1] = r4[1];
            bb[2 * p + 1][0] = r4[2]; bb[2 * p + 1][1] = r4[3];
        }
#pragma unroll
        for (int mi = 0; mi < 2; mi++)
#pragma unroll
            for (int ni = 0; ni < 8; ni++)
                mma_f16(acc[mi][ni], a[mi], bb[ni]);
    }

    const float* mp = mask + (size_t)(b & (NW - 1)) * NTOK * NTOK;
#pragma unroll
    for (int mi = 0; mi < 2; mi++) {
#pragma unroll
        for (int rh = 0; rh < 2; rh++) {
            const int row = rbase + mi * 16 + rh * 8 + g;
            const int o = rh * 2;
            float mx = -1e30f;
#pragma unroll
            for (int ni = 0; ni < 8; ni++) {
                float2 mv = *(const float2*)(mp + row * 64 + ni * 8 + 2 * tg);
                acc[mi][ni][o]     = fmaf(acc[mi][ni][o], scale, mv.x);
                acc[mi][ni][o + 1] = fmaf(acc[mi][ni][o + 1], scale, mv.y);
                mx = fmaxf(mx, fmaxf(acc[mi][ni][o], acc[mi][ni][o + 1]));
            }
            mx = fmaxf(mx, __shfl_xor_sync(0xffffffffu, mx, 1));
            mx = fmaxf(mx, __shfl_xor_sync(0xffffffffu, mx, 2));
            float sum = 0.f;
#pragma unroll
            for (int ni = 0; ni < 8; ni++) {
                acc[mi][ni][o]     = __expf(acc[mi][ni][o] - mx);
                acc[mi][ni][o + 1] = __expf(acc[mi][ni][o + 1] - mx);
                sum += acc[mi][ni][o] + acc[mi][ni][o + 1];
            }
            sum += __shfl_xor_sync(0xffffffffu, sum, 1);
            sum += __shfl_xor_sync(0xffffffffu, sum, 2);
            const float inv = 1.f / sum;
#pragma unroll
            for (int ni = 0; ni < 8; ni++) {
                acc[mi][ni][o]     *= inv;
                acc[mi][ni][o + 1] *= inv;
            }
        }
    }

    __half* Pw = Pp + w * 32 * AST;
#pragma unroll
    for (int mi = 0; mi < 2; mi++)
#pragma unroll
        for (int rh = 0; rh < 2; rh++) {
            const int rl = mi * 16 + rh * 8 + g;
#pragma unroll
            for (int ni = 0; ni < 8; ni++)
                *(__half2*)(Pw + rl * AST + ni * 8 + 2 * tg) =
                    __floats2half2_rn(acc[mi][ni][rh * 2], acc[mi][ni][rh * 2 + 1]);
        }
    __syncwarp();

    const uint32_t PwA = smem_u32(Pw);
    float acc2[2][4][4];
#pragma unroll
    for (int mi = 0; mi < 2; mi++)
#pragma unroll
        for (int ni = 0; ni < 4; ni++)
#pragma unroll
            for (int r = 0; r < 4; r++) acc2[mi][ni][r] = 0.f;

#pragma unroll
    for (int ks = 0; ks < 4; ks++) {
        uint32_t a[2][4], bb[4][2];
#pragma unroll
        for (int mi = 0; mi < 2; mi++)
            ldsm4(a[mi], PwA + (uint32_t)((mi * 16 + lmrow) * AST + ks * 16 + lmk) * 2);
#pragma unroll
        for (int p = 0; p < 2; p++) {
            uint32_t r4[4];
            int tok = ks * 16 + ((bg2 & 1) << 3) + bj;
            int chc = ch0 + p * 16 + ((bg2 >> 1) << 3);
            ldsm4t(r4, VsA + (uint32_t)(tok * AST + chc) * 2);
            bb[2 * p][0] = r4[0]; bb[2 * p][1] = r4[1];
            bb[2 * p + 1][0] = r4[2]; bb[2 * p + 1][1] = r4[3];
        }
#pragma unroll
        for (int mi = 0; mi < 2; mi++)
#pragma unroll
            for (int ni = 0; ni < 4; ni++)
                mma_f16(acc2[mi][ni], a[mi], bb[ni]);
    }

    CP_WAIT0();
    __syncthreads();

#pragma unroll
    for (int mi = 0; mi < 2; mi++) {
#pragma unroll
        for (int rh = 0; rh < 2; rh++) {
            const int row = rbase + mi * 16 + rh * 8 + g;
            const int py = row >> 3, px = row & 7;
#pragma unroll
            for (int ni = 0; ni < 4; ni++) {
#pragma unroll
                for (int c2 = 0; c2 < 2; c2++) {
                    const int c = ch0 + ni * 8 + 2 * tg + c2;
                    const float* wc9 = Wsm + c * 9;
                    float v = Bsm[c];
#pragma unroll
                    for (int dy = 0; dy < 3; dy++)
#pragma unroll
                        for (int dx = 0; dx < 3; dx++)
                            v = fmaf(__half2float(Halo[((py + dy) * 10 + px + dx) * HSTR + c]),
                                     wc9[dy * 3 + dx], v);
                    acc2[mi][ni][rh * 2 + c2] += v;
                }
            }
        }
    }

#pragma unroll
    for (int mi = 0; mi < 2; mi++) {
        const int row = rbase + mi * 16 + g;
#pragma unroll
        for (int ni = 0; ni < 4; ni++) {
            const int col = hp * 64 + ch0 + ni * 8 + 2 * tg;
            *(__half2*)(S + (size_t)(b * NTOK + row) * 256 + col) =
                __floats2half2_rn(acc2[mi][ni][0], acc2[mi][ni][1]);
            *(__half2*)(S + (size_t)(b * NTOK + row + 8) * 256 + col) =
                __floats2half2_rn(acc2[mi][ni][2], acc2[mi][ni][3]);
        }
    }
}

// ---------------------------------------------------------------------------
// kernel_launch
// ---------------------------------------------------------------------------
extern "C" void kernel_launch(void* const* d_in, const int* in_sizes, int n_in,
                              void* d_out, int out_size)
{
    const float* x    = (const float*)d_in[0];
    const float* y    = (const float*)d_in[1];
    const float* mask = (const float*)d_in[2];
    const float* Wq   = (const float*)d_in[3];
    const float* bq   = (const float*)d_in[4];
    const float* Wk   = (const float*)d_in[5];
    const float* bk   = (const float*)d_in[6];
    const float* Wv   = (const float*)d_in[7];
    const float* bv   = (const float*)d_in[8];
    const float* rw   = (const float*)d_in[9];
    const float* rb   = (const float*)d_in[10];
    const float* Wp   = (const float*)d_in[11];
    const float* bp   = (const float*)d_in[12];
    float* out        = (float*)d_out;

    __half *pxh, *pyh, *pWq, *pWk, *pWv, *pWp, *pQ, *pK, *pV, *pS;
    cudaGetSymbolAddress((void**)&pxh, g_xh);
    cudaGetSymbolAddress((void**)&pyh, g_yh);
    cudaGetSymbolAddress((void**)&pWq, g_Wqh);
    cudaGetSymbolAddress((void**)&pWk, g_Wkh);
    cudaGetSymbolAddress((void**)&pWv, g_Wvh);
    cudaGetSymbolAddress((void**)&pWp, g_Wph);
    cudaGetSymbolAddress((void**)&pQ, g_Q);
    cudaGetSymbolAddress((void**)&pK, g_K);
    cudaGetSymbolAddress((void**)&pV, g_V);
    cudaGetSymbolAddress((void**)&pS, g_S);

    static bool attr_done = false;
    if (!attr_done) {
        cudaFuncSetAttribute(gemm_f16k<__half>, cudaFuncAttributeMaxDynamicSharedMemorySize, GEMM_SMEM);
        cudaFuncSetAttribute(gemm_f16k<float>,  cudaFuncAttributeMaxDynamicSharedMemorySize, GEMM_SMEM);
        cudaFuncSetAttribute(attn_lepe, cudaFuncAttributeMaxDynamicSharedMemorySize, ATTN_SMEM);
        attr_done = true;
    }

    const int NBIG = (int)((size_t)MTOT * CH / (256 * 8));   // 32768 blocks
    cvt_f16<<<NBIG, 256>>>(x, pxh);
    cvt_f16<<<NBIG, 256>>>(y, pyh);
    cvt_w4<<<128, 256>>>(Wq, Wk, Wv, Wp, pWq, pWk, pWv, pWp);

    // Q, V, K in ONE launch: wsel = blockIdx.x>>1 -> {x*Wq, x*Wv, y*Wk}
    gemm_f16k<__half><<<dim3(6, MTOT / 128), 256, GEMM_SMEM>>>(
        pxh, pyh, pWq, pWv, pWk, bq, bv, bk, pQ, pV, pK);

    attn_lepe<<<dim3(4, BWIN), 128, ATTN_SMEM>>>(pQ, pK, pV, mask, rw, rb, pS);

    gemm_f16k<float><<<dim3(2, MTOT / 128), 256, GEMM_SMEM>>>(
        pS, pS, pWp, pWp, pWp, bp, bp, bp, out, out, out);
}